// round 5
// baseline (speedup 1.0000x reference)
#include <cuda_runtime.h>
#include <cstdint>

#define N_TOT 32768
#define DIM   64
#define KCODES 1024
#define BM    128
#define NTHR  256
#define NCHUNK 16   // K / 64

// output offsets (float32 elements), concatenated in reference return order
#define O_QV   0           // [32,64,32,32] = 2097152
#define O_IDX  2097152     // [32,1,32,32]  = 32768
#define O_LOSS 2129920     // scalar
#define O_EMB  2129921     // [1024,64]  (ODD offset -> no vector stores!)
#define O_CL   2195457     // [1024]
#define O_EMA  2196481     // [1024,64]  (ODD offset -> no vector stores!)

typedef unsigned long long u64;

// scratch (allocation-free rule: __device__ globals)
__device__ float g_dw[KCODES * DIM];
__device__ float g_ni[KCODES];
__device__ float g_ee[KCODES];
__device__ float g_loss;

__device__ __forceinline__ u64 dup_f(float a) {
    u64 r; asm("mov.b64 %0, {%1,%1};" : "=l"(r) : "f"(a)); return r;
}
__device__ __forceinline__ u64 pk(float a, float b) {
    u64 r; asm("mov.b64 %0, {%1,%2};" : "=l"(r) : "f"(a), "f"(b)); return r;
}
__device__ __forceinline__ void fma2(u64& acc, u64 a, u64 b) {
    asm("fma.rn.f32x2 %0, %1, %2, %0;" : "+l"(acc) : "l"(a), "l"(b));
}
__device__ __forceinline__ void unpk(u64 v, float& lo, float& hi) {
    asm("mov.b64 {%0,%1}, %2;" : "=f"(lo), "=f"(hi) : "l"(v));
}

// ---------------------------------------------------------------------------
// Kernel 0: zero scratch, precompute ||e_k||^2
// ---------------------------------------------------------------------------
__global__ void k_init(const float* __restrict__ emb) {
    int t = blockIdx.x * blockDim.x + threadIdx.x;   // 16384 threads
    reinterpret_cast<float4*>(g_dw)[t] = make_float4(0.f, 0.f, 0.f, 0.f);
    if (t < KCODES) {
        g_ni[t] = 0.0f;
        const float4* e4 = reinterpret_cast<const float4*>(emb + (size_t)t * DIM);
        float s = 0.0f;
#pragma unroll
        for (int i = 0; i < 16; i++) {
            float4 v = e4[i];
            s += v.x * v.x + v.y * v.y + v.z * v.z + v.w * v.w;
        }
        g_ee[t] = s;
    }
    if (t == 0) g_loss = 0.0f;
}

// nop: pads the launch sequence so ncu's skip-5 capture lands on k_main
__global__ void k_nop() {}

// ---------------------------------------------------------------------------
// Kernel 1: distances + argmin + fused epilogue
//   Dynamic smem 64KB: zs[64][128] (32KB) + double-buffered es (2 x 16KB).
//   Per chunk: prefetch next e-chunk into regs, run d-loop on current buffer,
//   STS prefetch into other buffer, ONE __syncthreads.
// ---------------------------------------------------------------------------
__global__ __launch_bounds__(NTHR, 2)
void k_main(const float* __restrict__ z, const float* __restrict__ emb,
            float* __restrict__ out) {
    extern __shared__ __align__(16) unsigned char sm[];
    float* zs  = reinterpret_cast<float*>(sm);           // [64][128] zs[d*128+m]
    float* esb = reinterpret_cast<float*>(sm + 32768);   // 2 x [64][64]
    u64*   smin = reinterpret_cast<u64*>(sm + 32768);    // alias es buf0 (post-loop)
    int*   sidx = reinterpret_cast<int*>(sm + 32768 + BM * 8);
    float* lred = reinterpret_cast<float*>(sm);          // alias zs (very end)

    const int tid = threadIdx.x;
    const int tx  = tid & 15;
    const int ty  = tid >> 4;
    const int row0 = blockIdx.x * BM;

    // ---- load z tile transposed to zs[d][m]
    for (int i = tid; i < BM * 16; i += NTHR) {
        int m  = (i & 15) | ((i >> 8) << 4);
        int dq = (i >> 4) & 15;
        float4 v = *reinterpret_cast<const float4*>(z + (size_t)(row0 + m) * DIM + dq * 4);
        zs[(dq * 4 + 0) * BM + m] = v.x;
        zs[(dq * 4 + 1) * BM + m] = v.y;
        zs[(dq * 4 + 2) * BM + m] = v.z;
        zs[(dq * 4 + 3) * BM + m] = v.w;
    }

    // ---- load chunk 0 into buffer 0 (per-thread: kk = tx|(j<<4), dq = ty)
    {
#pragma unroll
        for (int j = 0; j < 4; j++) {
            int kk = tx | (j << 4);
            float4 v = *reinterpret_cast<const float4*>(emb + (size_t)kk * DIM + ty * 4);
            esb[(ty * 4 + 0) * 64 + kk] = v.x;
            esb[(ty * 4 + 1) * 64 + kk] = v.y;
            esb[(ty * 4 + 2) * 64 + kk] = v.z;
            esb[(ty * 4 + 3) * 64 + kk] = v.w;
        }
    }
    __syncthreads();

    float    best[8];
    unsigned bidx[8];
#pragma unroll
    for (int r = 0; r < 8; r++) { best[r] = 3.4e38f; bidx[r] = 0u; }

    for (int c = 0; c < NCHUNK; c++) {
        const int k0 = c * 64;
        const float* es = esb + (c & 1) * 4096;

        // prefetch next chunk into registers (latency hidden by the d-loop)
        float4 pf0, pf1, pf2, pf3;
        if (c < NCHUNK - 1) {
            const float* src = emb + (size_t)(k0 + 64) * DIM + ty * 4;
            pf0 = *reinterpret_cast<const float4*>(src + (size_t)(tx)      * DIM);
            pf1 = *reinterpret_cast<const float4*>(src + (size_t)(tx + 16) * DIM);
            pf2 = *reinterpret_cast<const float4*>(src + (size_t)(tx + 32) * DIM);
            pf3 = *reinterpret_cast<const float4*>(src + (size_t)(tx + 48) * DIM);
        }

        // acc[j*4+p]: code tx*4+j, row pair (ty*8+2p, ty*8+2p+1)
        u64 acc[16];
#pragma unroll
        for (int i = 0; i < 16; i++) acc[i] = 0ULL;

        const float* zp_base = zs + ty * 8;
        const float* ep_base = es + tx * 4;
#pragma unroll 4
        for (int d = 0; d < DIM; d++) {
            float4 za = *reinterpret_cast<const float4*>(zp_base + d * BM);
            float4 zb = *reinterpret_cast<const float4*>(zp_base + d * BM + 4);
            float4 ef = *reinterpret_cast<const float4*>(ep_base + d * 64);
            u64 zp0 = pk(za.x, za.y), zp1 = pk(za.z, za.w);
            u64 zp2 = pk(zb.x, zb.y), zp3 = pk(zb.z, zb.w);
            u64 e0 = dup_f(ef.x), e1 = dup_f(ef.y), e2 = dup_f(ef.z), e3 = dup_f(ef.w);
            fma2(acc[0],  zp0, e0); fma2(acc[1],  zp1, e0);
            fma2(acc[2],  zp2, e0); fma2(acc[3],  zp3, e0);
            fma2(acc[4],  zp0, e1); fma2(acc[5],  zp1, e1);
            fma2(acc[6],  zp2, e1); fma2(acc[7],  zp3, e1);
            fma2(acc[8],  zp0, e2); fma2(acc[9],  zp1, e2);
            fma2(acc[10], zp2, e2); fma2(acc[11], zp3, e2);
            fma2(acc[12], zp0, e3); fma2(acc[13], zp1, e3);
            fma2(acc[14], zp2, e3); fma2(acc[15], zp3, e3);
        }

        // chunk epilogue: dist = ||e||^2 - 2*dot
        float eek[4];
#pragma unroll
        for (int j = 0; j < 4; j++) eek[j] = __ldg(&g_ee[k0 + tx * 4 + j]);
#pragma unroll
        for (int j = 0; j < 4; j++) {
#pragma unroll
            for (int p = 0; p < 4; p++) {
                float d0, d1;
                unpk(acc[j * 4 + p], d0, d1);
                float dist0 = fmaf(-2.0f, d0, eek[j]);
                float dist1 = fmaf(-2.0f, d1, eek[j]);
                unsigned kj = (unsigned)(k0 + tx * 4 + j);
                if (dist0 < best[2 * p])     { best[2 * p]     = dist0; bidx[2 * p]     = kj; }
                if (dist1 < best[2 * p + 1]) { best[2 * p + 1] = dist1; bidx[2 * p + 1] = kj; }
            }
        }

        // store prefetched chunk into the other buffer
        if (c < NCHUNK - 1) {
            float* en = esb + ((c + 1) & 1) * 4096;
            en[(ty * 4 + 0) * 64 + (tx)]      = pf0.x;
            en[(ty * 4 + 1) * 64 + (tx)]      = pf0.y;
            en[(ty * 4 + 2) * 64 + (tx)]      = pf0.z;
            en[(ty * 4 + 3) * 64 + (tx)]      = pf0.w;
            en[(ty * 4 + 0) * 64 + (tx + 16)] = pf1.x;
            en[(ty * 4 + 1) * 64 + (tx + 16)] = pf1.y;
            en[(ty * 4 + 2) * 64 + (tx + 16)] = pf1.z;
            en[(ty * 4 + 3) * 64 + (tx + 16)] = pf1.w;
            en[(ty * 4 + 0) * 64 + (tx + 32)] = pf2.x;
            en[(ty * 4 + 1) * 64 + (tx + 32)] = pf2.y;
            en[(ty * 4 + 2) * 64 + (tx + 32)] = pf2.z;
            en[(ty * 4 + 3) * 64 + (tx + 32)] = pf2.w;
            en[(ty * 4 + 0) * 64 + (tx + 48)] = pf3.x;
            en[(ty * 4 + 1) * 64 + (tx + 48)] = pf3.y;
            en[(ty * 4 + 2) * 64 + (tx + 48)] = pf3.z;
            en[(ty * 4 + 3) * 64 + (tx + 48)] = pf3.w;
        }
        __syncthreads();
    }

    // ---- cross-thread argmin reduce per row (packed key, low-index tiebreak)
    if (tid < BM) smin[tid] = 0xFFFFFFFFFFFFFFFFULL;
    __syncthreads();
#pragma unroll
    for (int r = 0; r < 8; r++) {
        unsigned u = __float_as_uint(best[r]);
        u = (u & 0x80000000u) ? ~u : (u | 0x80000000u);
        u64 key = ((u64)u << 32) | (u64)bidx[r];
        atomicMin(&smin[ty * 8 + r], key);
    }
    __syncthreads();

    if (tid < BM) {
        int idx = (int)(smin[tid] & 0xFFFFFFFFull);
        sidx[tid] = idx;
        int row = row0 + tid;
        out[O_IDX + row] = (float)idx;
        atomicAdd(&g_ni[idx], 1.0f);
    }
    __syncthreads();

    // ---- fused epilogue: quantized gather + transposed write + loss + dw scatter
    float lacc = 0.0f;
    for (int i = tid; i < BM * DIM; i += NTHR) {
        int m = i & (BM - 1);
        int d = i >> 7;
        int row = row0 + m;
        int idx = sidx[m];
        float zv = zs[d * BM + m];
        float q  = __ldg(&emb[(size_t)idx * DIM + d]);
        float diff = q - zv;
        lacc += diff * diff;
        int b  = row >> 10;
        int hw = row & 1023;
        out[O_QV + (((size_t)(b * DIM + d)) << 10) + hw] = zv + diff;
        atomicAdd(&g_dw[idx * DIM + d], zv);
    }

#pragma unroll
    for (int o = 16; o > 0; o >>= 1) lacc += __shfl_xor_sync(0xFFFFFFFFu, lacc, o);
    __syncthreads();
    if ((tid & 31) == 0) lred[tid >> 5] = lacc;
    __syncthreads();
    if (tid == 0) {
        float s = 0.0f;
#pragma unroll
        for (int w = 0; w < NTHR / 32; w++) s += lred[w];
        atomicAdd(&g_loss, s);
    }
}

// ---------------------------------------------------------------------------
// Kernel 2 (fused): smoothing + EMA + new embeddings.
// ---------------------------------------------------------------------------
__global__ __launch_bounds__(256)
void k_final(const float* __restrict__ cs, const float* __restrict__ ema,
             float* __restrict__ out) {
    __shared__ float red[8];
    const int tid = threadIdx.x;

    float part = 0.0f;
#pragma unroll
    for (int k = tid; k < KCODES; k += 256)
        part += cs[k] * 0.99f + g_ni[k] * 0.01f;
#pragma unroll
    for (int o = 16; o > 0; o >>= 1) part += __shfl_xor_sync(0xFFFFFFFFu, part, o);
    if ((tid & 31) == 0) red[tid >> 5] = part;
    __syncthreads();
    float n = 0.0f;
#pragma unroll
    for (int w = 0; w < 8; w++) n += red[w];

    if (blockIdx.x == 0 && tid == 0)
        out[O_LOSS] = 0.25f * g_loss / 2097152.0f;

    const int i0 = (blockIdx.x * 256 + tid) * 4;   // element base, < 65536
    const int k  = i0 >> 6;
    float raw = cs[k] * 0.99f + g_ni[k] * 0.01f;
    float smooth = (raw + 1e-5f) / (n + 1024.0f * 1e-5f) * n;
    if ((i0 & 63) == 0) out[O_CL + k] = smooth;

    float4 ev = *reinterpret_cast<const float4*>(ema + i0);
    float4 dv = *reinterpret_cast<const float4*>(g_dw + i0);
    float inv = 1.0f / smooth;
    float ne0 = ev.x * 0.99f + dv.x * 0.01f;
    float ne1 = ev.y * 0.99f + dv.y * 0.01f;
    float ne2 = ev.z * 0.99f + dv.z * 0.01f;
    float ne3 = ev.w * 0.99f + dv.w * 0.01f;
    // scalar stores: O_EMA / O_EMB are odd element offsets (4B-aligned only)
    out[O_EMA + i0 + 0] = ne0;  out[O_EMB + i0 + 0] = ne0 * inv;
    out[O_EMA + i0 + 1] = ne1;  out[O_EMB + i0 + 1] = ne1 * inv;
    out[O_EMA + i0 + 2] = ne2;  out[O_EMB + i0 + 2] = ne2 * inv;
    out[O_EMA + i0 + 3] = ne3;  out[O_EMB + i0 + 3] = ne3 * inv;
}

// ---------------------------------------------------------------------------
extern "C" void kernel_launch(void* const* d_in, const int* in_sizes, int n_in,
                              void* d_out, int out_size) {
    const float* z   = (const float*)d_in[0];
    const float* emb = (const float*)d_in[1];
    const float* cs  = (const float*)d_in[2];
    const float* ema = (const float*)d_in[3];
    float* out = (float*)d_out;

    static bool attr_set = false;
    if (!attr_set) {
        cudaFuncSetAttribute(k_main, cudaFuncAttributeMaxDynamicSharedMemorySize, 65536);
        attr_set = true;
    }

    // order chosen so ncu's skip-5 capture lands on k_main (indices 1,5,9,...)
    k_init<<<64, 256>>>(emb);
    k_main<<<N_TOT / BM, NTHR, 65536>>>(z, emb, out);
    k_final<<<64, 256>>>(cs, ema, out);
    k_nop<<<1, 32>>>();
}

// round 7
// speedup vs baseline: 1.3760x; 1.3760x over previous
#include <cuda_runtime.h>
#include <cuda_bf16.h>
#include <cstdint>

#define N_TOT  32768
#define DIM    64
#define KCODES 1024
#define BM     128
#define NTHR   256
#define NCHUNK 8      // 1024 codes / 128 per chunk
#define NCK    128    // codes per chunk

// output offsets (float32 elements), concatenated in reference return order
#define O_QV   0
#define O_IDX  2097152
#define O_LOSS 2129920
#define O_EMB  2129921     // ODD offset -> scalar stores only
#define O_CL   2195457
#define O_EMA  2196481     // ODD offset -> scalar stores only

typedef unsigned long long u64;
typedef unsigned int u32;

// ---- scratch (__device__ globals; no allocations allowed) ----
__device__ float g_dw[KCODES * DIM];
__device__ float g_ni[KCODES];
__device__ float g_ee[KCODES];
__device__ float g_loss;
__device__ uint4 g_esplit[3][KCODES * 8];   // 3 bf16 split terms, [1024 codes][128B rows]

// ---- smem layout (dynamic, 98304 B -> 2 blocks/SM) ----
#define A_OFF    0          // 3 x 16KB bf16 A tiles (SW128), z split
#define B_OFF    49152      // 3 x 16KB bf16 B tiles (SW128), e split chunk
#define SMEM_SZ  98304

#define SW128(b) ((b) ^ (((b) >> 3) & 0x70))

__device__ __forceinline__ u32 smem_u32(const void* p) {
    u32 a;
    asm("{ .reg .u64 t; cvta.to.shared.u64 t, %1; cvt.u32.u64 %0, t; }" : "=r"(a) : "l"(p));
    return a;
}
#define LDSM_X4(r, addr) \
    asm volatile("ldmatrix.sync.aligned.m8n8.x4.shared.b16 {%0,%1,%2,%3}, [%4];" \
        : "=r"((r)[0]), "=r"((r)[1]), "=r"((r)[2]), "=r"((r)[3]) : "r"(addr))
#define LDSM_X2(r, addr) \
    asm volatile("ldmatrix.sync.aligned.m8n8.x2.shared.b16 {%0,%1}, [%2];" \
        : "=r"((r)[0]), "=r"((r)[1]) : "r"(addr))
#define MMA_BF16(c, a, b) \
    asm volatile("mma.sync.aligned.m16n8k16.row.col.f32.bf16.bf16.f32 " \
        "{%0,%1,%2,%3}, {%4,%5,%6,%7}, {%8,%9}, {%0,%1,%2,%3};" \
        : "+f"((c)[0]), "+f"((c)[1]), "+f"((c)[2]), "+f"((c)[3]) \
        : "r"((a)[0]), "r"((a)[1]), "r"((a)[2]), "r"((a)[3]), \
          "r"((b)[0]), "r"((b)[1]))

__device__ __forceinline__ void split3(float x, u32& h0, u32& h1, u32& h2) {
    __nv_bfloat16 b0 = __float2bfloat16(x);
    float f0 = __bfloat162float(b0);
    float r = x - f0;
    __nv_bfloat16 b1 = __float2bfloat16(r);
    float f1 = __bfloat162float(b1);
    __nv_bfloat16 b2 = __float2bfloat16(r - f1);
    h0 = (u32)__bfloat16_as_ushort(b0);
    h1 = (u32)__bfloat16_as_ushort(b1);
    h2 = (u32)__bfloat16_as_ushort(b2);
}
__device__ __forceinline__ float bf_lo(u32 w) {
    return __bfloat162float(__ushort_as_bfloat16((unsigned short)(w & 0xffffu)));
}
__device__ __forceinline__ float bf_hi(u32 w) {
    return __bfloat162float(__ushort_as_bfloat16((unsigned short)(w >> 16)));
}
__device__ __forceinline__ u64 pack_key(float v, u32 k) {
    u32 u = __float_as_uint(v);
    u = (u & 0x80000000u) ? ~u : (u | 0x80000000u);
    return ((u64)u << 32) | (u64)k;
}

// ---------------------------------------------------------------------------
// Kernel 0: zero scratch, ||e||^2, split embeddings into 3 bf16 arrays
// ---------------------------------------------------------------------------
__global__ void k_prep(const float* __restrict__ emb) {
    int t = blockIdx.x * blockDim.x + threadIdx.x;   // 16384 threads
    reinterpret_cast<float4*>(g_dw)[t] = make_float4(0.f, 0.f, 0.f, 0.f);
    {
        int code = t >> 4, dq = t & 15;
        float4 v = __ldg(reinterpret_cast<const float4*>(emb) + t);
        u32 h0[4], h1[4], h2[4];
        split3(v.x, h0[0], h1[0], h2[0]);
        split3(v.y, h0[1], h1[1], h2[1]);
        split3(v.z, h0[2], h1[2], h2[2]);
        split3(v.w, h0[3], h1[3], h2[3]);
        u32 base = code * 32 + dq * 2;
        u32* p0 = reinterpret_cast<u32*>(g_esplit[0]);
        u32* p1 = reinterpret_cast<u32*>(g_esplit[1]);
        u32* p2 = reinterpret_cast<u32*>(g_esplit[2]);
        p0[base] = h0[0] | (h0[1] << 16);  p0[base + 1] = h0[2] | (h0[3] << 16);
        p1[base] = h1[0] | (h1[1] << 16);  p1[base + 1] = h1[2] | (h1[3] << 16);
        p2[base] = h2[0] | (h2[1] << 16);  p2[base + 1] = h2[2] | (h2[3] << 16);
    }
    if (t < KCODES) {
        g_ni[t] = 0.0f;
        const float4* e4 = reinterpret_cast<const float4*>(emb + (size_t)t * DIM);
        float s = 0.0f;
#pragma unroll
        for (int i = 0; i < 16; i++) {
            float4 v = e4[i];
            s += v.x * v.x + v.y * v.y + v.z * v.z + v.w * v.w;
        }
        g_ee[t] = s;
    }
    if (t == 0) g_loss = 0.0f;
}

// ---------------------------------------------------------------------------
// Kernel 1: HMMA distances (6-term bf16 split) + argmin + fused epilogue
// ---------------------------------------------------------------------------
__global__ __launch_bounds__(NTHR, 2)
void k_main(const float* __restrict__ z, const float* __restrict__ emb,
            float* __restrict__ out) {
    extern __shared__ __align__(16) unsigned char sm[];
    int*   sidx = reinterpret_cast<int*>(sm + B_OFF);     // alias B (post-loop)
    float* lred = reinterpret_cast<float*>(sm + B_OFF + 2048);

    const u32 smb = smem_u32(sm);
    const int tid  = threadIdx.x;
    const int lane = tid & 31;
    const int wid  = tid >> 5;
    const int wrow = wid * 16;
    const int row0 = blockIdx.x * BM;

    // ---- build 3 bf16 A tiles from z (SW128, [128 rows][64 d])
    for (int i = tid; i < BM * 16; i += NTHR) {
        int m = i >> 4, dq = i & 15;
        float4 v = *reinterpret_cast<const float4*>(z + (size_t)(row0 + m) * DIM + dq * 4);
        u32 h0[4], h1[4], h2[4];
        split3(v.x, h0[0], h1[0], h2[0]);
        split3(v.y, h0[1], h1[1], h2[1]);
        split3(v.z, h0[2], h1[2], h2[2]);
        split3(v.w, h0[3], h1[3], h2[3]);
        u32 sw = SW128((u32)(m * 128 + dq * 8));
#pragma unroll
        for (int t = 0; t < 3; t++) {
            u32* hh = (t == 0) ? h0 : (t == 1) ? h1 : h2;
            u32* dst = reinterpret_cast<u32*>(sm + A_OFF + t * 16384 + sw);
            dst[0] = hh[0] | (hh[1] << 16);
            dst[1] = hh[2] | (hh[3] << 16);
        }
    }
    __syncthreads();

    // ---- load A fragments into registers (persist for whole kernel)
    u32 afr[3][4][4];
    {
        int g = lane >> 3;
        int arow = wrow + (g & 1) * 8 + (lane & 7);
        int acol = (g >> 1) * 16;
#pragma unroll
        for (int t = 0; t < 3; t++)
#pragma unroll
            for (int kt = 0; kt < 4; kt++) {
                u32 addr = smb + A_OFF + t * 16384 +
                           SW128((u32)(arow * 128 + kt * 32 + acol));
                LDSM_X4(afr[t][kt], addr);
            }
    }

    float best0 = 3.4e38f, best1 = 3.4e38f;
    u32   idx0 = 0, idx1 = 0;

    const int brow = lane & 7;
    const int bcol = ((lane >> 3) & 1) * 16;

    for (int c = 0; c < NCHUNK; c++) {
        __syncthreads();   // previous chunk's ldmatrix reads done
        // ---- stage B chunk (3 terms x 128 codes x 128B) swizzled
        for (int u = tid; u < 3072; u += NTHR) {
            int term = u >> 10;
            int rem  = u & 1023;
            int krow = rem >> 3;
            int seg  = rem & 7;
            uint4 v = __ldg(&g_esplit[term][(c * NCK + krow) * 8 + seg]);
            u32 sw = SW128((u32)(krow * 128 + seg * 16));
            *reinterpret_cast<uint4*>(sm + B_OFF + term * 16384 + sw) = v;
        }
        __syncthreads();

        for (int nt = 0; nt < 16; nt++) {
            // load 12 B fragments (3 terms x 4 k-tiles)
            u32 bb[3][4][2];
            int rbase = (nt * 8 + brow) * 128 + bcol;
#pragma unroll
            for (int t = 0; t < 3; t++)
#pragma unroll
                for (int kt = 0; kt < 4; kt++) {
                    u32 addr = smb + B_OFF + t * 16384 + SW128((u32)(rbase + kt * 32));
                    LDSM_X2(bb[t][kt], addr);
                }

            float cc[4] = {0.f, 0.f, 0.f, 0.f};
            // small terms first: (2,0),(0,2),(1,1),(1,0),(0,1),(0,0)
#pragma unroll
            for (int kt = 0; kt < 4; kt++) MMA_BF16(cc, afr[2][kt], bb[0][kt]);
#pragma unroll
            for (int kt = 0; kt < 4; kt++) MMA_BF16(cc, afr[0][kt], bb[2][kt]);
#pragma unroll
            for (int kt = 0; kt < 4; kt++) MMA_BF16(cc, afr[1][kt], bb[1][kt]);
#pragma unroll
            for (int kt = 0; kt < 4; kt++) MMA_BF16(cc, afr[1][kt], bb[0][kt]);
#pragma unroll
            for (int kt = 0; kt < 4; kt++) MMA_BF16(cc, afr[0][kt], bb[1][kt]);
#pragma unroll
            for (int kt = 0; kt < 4; kt++) MMA_BF16(cc, afr[0][kt], bb[0][kt]);

            // dist = ||e||^2 - 2*dot; frag layout: rows lane>>2 (+8), cols 2*(lane&3)+{0,1}
            u32 kc = (u32)(c * NCK + nt * 8 + 2 * (lane & 3));
            float e0 = __ldg(&g_ee[kc]), e1 = __ldg(&g_ee[kc + 1]);
            float d00 = fmaf(-2.0f, cc[0], e0);
            float d01 = fmaf(-2.0f, cc[1], e1);
            float cv0 = (d01 < d00) ? d01 : d00;
            u32   ck0 = (d01 < d00) ? kc + 1 : kc;
            if (cv0 < best0) { best0 = cv0; idx0 = ck0; }
            float d10 = fmaf(-2.0f, cc[2], e0);
            float d11 = fmaf(-2.0f, cc[3], e1);
            float cv1 = (d11 < d10) ? d11 : d10;
            u32   ck1 = (d11 < d10) ? kc + 1 : kc;
            if (cv1 < best1) { best1 = cv1; idx1 = ck1; }
        }
    }

    // ---- reduce argmin across the 4 lanes sharing each row
    u64 key0 = pack_key(best0, idx0);
    u64 key1 = pack_key(best1, idx1);
#pragma unroll
    for (int o = 1; o <= 2; o <<= 1) {
        u64 t0 = __shfl_xor_sync(0xFFFFFFFFu, key0, o);
        u64 t1 = __shfl_xor_sync(0xFFFFFFFFu, key1, o);
        if (t0 < key0) key0 = t0;
        if (t1 < key1) key1 = t1;
    }
    __syncthreads();   // all mainloop B reads complete -> safe to alias
    if ((lane & 3) == 0) {
        int r0 = wrow + (lane >> 2);
        int i0 = (int)(key0 & 0xFFFFFFFFull);
        int i1 = (int)(key1 & 0xFFFFFFFFull);
        sidx[r0]     = i0;
        sidx[r0 + 8] = i1;
        out[O_IDX + row0 + r0]     = (float)i0;
        out[O_IDX + row0 + r0 + 8] = (float)i1;
        atomicAdd(&g_ni[i0], 1.0f);
        atomicAdd(&g_ni[i1], 1.0f);
    }
    __syncthreads();

    // ---- fused epilogue: reconstruct z from A tiles (z = b0+b1+b2, ~1e-8 err)
    float lacc = 0.0f;
    for (int i = tid; i < BM * 32; i += NTHR) {   // (d-pair, m): m fast
        int d2 = i >> 7;          // 0..31 -> d = 2*d2
        int m  = i & 127;
        u32 sw = SW128((u32)(m * 128 + d2 * 4));
        u32 w0 = *reinterpret_cast<u32*>(sm + A_OFF + sw);
        u32 w1 = *reinterpret_cast<u32*>(sm + A_OFF + 16384 + sw);
        u32 w2 = *reinterpret_cast<u32*>(sm + A_OFF + 32768 + sw);
        float zlo = bf_lo(w0) + bf_lo(w1) + bf_lo(w2);
        float zhi = bf_hi(w0) + bf_hi(w1) + bf_hi(w2);
        int idx = sidx[m];
        int d = d2 * 2;
        float2 q = __ldg(reinterpret_cast<const float2*>(emb + (size_t)idx * DIM + d));
        float dlo = q.x - zlo, dhi = q.y - zhi;
        lacc += dlo * dlo + dhi * dhi;
        int row = row0 + m;
        int b = row >> 10, hw = row & 1023;
        size_t obase = ((size_t)(b * DIM + d) << 10) + hw;
        out[O_QV + obase]        = zlo + dlo;
        out[O_QV + obase + 1024] = zhi + dhi;
        atomicAdd(&g_dw[idx * DIM + d],     zlo);
        atomicAdd(&g_dw[idx * DIM + d + 1], zhi);
    }
#pragma unroll
    for (int o = 16; o > 0; o >>= 1) lacc += __shfl_xor_sync(0xFFFFFFFFu, lacc, o);
    if (lane == 0) lred[wid] = lacc;
    __syncthreads();
    if (tid == 0) {
        float s = 0.0f;
#pragma unroll
        for (int w = 0; w < NTHR / 32; w++) s += lred[w];
        atomicAdd(&g_loss, s);
    }
}

// ---------------------------------------------------------------------------
// Kernel 2: smoothing + EMA + new embeddings
// ---------------------------------------------------------------------------
__global__ __launch_bounds__(256)
void k_final(const float* __restrict__ cs, const float* __restrict__ ema,
             float* __restrict__ out) {
    __shared__ float red[8];
    const int tid = threadIdx.x;

    float part = 0.0f;
#pragma unroll
    for (int k = tid; k < KCODES; k += 256)
        part += cs[k] * 0.99f + g_ni[k] * 0.01f;
#pragma unroll
    for (int o = 16; o > 0; o >>= 1) part += __shfl_xor_sync(0xFFFFFFFFu, part, o);
    if ((tid & 31) == 0) red[tid >> 5] = part;
    __syncthreads();
    float n = 0.0f;
#pragma unroll
    for (int w = 0; w < 8; w++) n += red[w];

    if (blockIdx.x == 0 && tid == 0)
        out[O_LOSS] = 0.25f * g_loss / 2097152.0f;

    const int i0 = (blockIdx.x * 256 + tid) * 4;
    const int k  = i0 >> 6;
    float raw = cs[k] * 0.99f + g_ni[k] * 0.01f;
    float smooth = (raw + 1e-5f) / (n + 1024.0f * 1e-5f) * n;
    if ((i0 & 63) == 0) out[O_CL + k] = smooth;

    float4 ev = *reinterpret_cast<const float4*>(ema + i0);
    float4 dv = *reinterpret_cast<const float4*>(g_dw + i0);
    float inv = 1.0f / smooth;
    float ne0 = ev.x * 0.99f + dv.x * 0.01f;
    float ne1 = ev.y * 0.99f + dv.y * 0.01f;
    float ne2 = ev.z * 0.99f + dv.z * 0.01f;
    float ne3 = ev.w * 0.99f + dv.w * 0.01f;
    out[O_EMA + i0 + 0] = ne0;  out[O_EMB + i0 + 0] = ne0 * inv;
    out[O_EMA + i0 + 1] = ne1;  out[O_EMB + i0 + 1] = ne1 * inv;
    out[O_EMA + i0 + 2] = ne2;  out[O_EMB + i0 + 2] = ne2 * inv;
    out[O_EMA + i0 + 3] = ne3;  out[O_EMB + i0 + 3] = ne3 * inv;
}

// ---------------------------------------------------------------------------
extern "C" void kernel_launch(void* const* d_in, const int* in_sizes, int n_in,
                              void* d_out, int out_size) {
    const float* z   = (const float*)d_in[0];
    const float* emb = (const float*)d_in[1];
    const float* cs  = (const float*)d_in[2];
    const float* ema = (const float*)d_in[3];
    float* out = (float*)d_out;

    static bool attr_set = false;
    if (!attr_set) {
        cudaFuncSetAttribute(k_main, cudaFuncAttributeMaxDynamicSharedMemorySize, SMEM_SZ);
        attr_set = true;
    }

    k_prep<<<64, 256>>>(emb);
    k_main<<<N_TOT / BM, NTHR, SMEM_SZ>>>(z, emb, out);
    k_final<<<64, 256>>>(cs, ema, out);
}

// round 8
// speedup vs baseline: 1.4175x; 1.0302x over previous
#include <cuda_runtime.h>
#include <cuda_bf16.h>
#include <cstdint>

#define N_TOT  32768
#define DIM    64
#define KCODES 1024
#define BM     128
#define NTHR   256
#define NCHUNK 8      // 1024 codes / 128 per chunk
#define NCK    128    // codes per chunk

// output offsets (float32 elements), concatenated in reference return order
#define O_QV   0
#define O_IDX  2097152
#define O_LOSS 2129920
#define O_EMB  2129921     // ODD offset -> scalar stores only
#define O_CL   2195457
#define O_EMA  2196481     // ODD offset -> scalar stores only

typedef unsigned long long u64;
typedef unsigned int u32;

// ---- scratch (__device__ globals; no allocations allowed) ----
__device__ float g_dw[KCODES * DIM];
__device__ float g_ni[KCODES];
__device__ float g_ee[KCODES];
__device__ float g_loss;
__device__ uint4 g_esplit[3][KCODES * 8];   // 3 bf16 split terms, [1024 codes][128B rows]

// ---- smem layout (dynamic, 102400 B -> 2 blocks/SM) ----
#define A_OFF    0          // 3 x 16KB bf16 A tiles (SW128), z split
#define B_OFF    49152      // 3 x 16KB bf16 B tiles (SW128), e split chunk
#define EE_OFF   98304      // 1024 floats ||e||^2
#define SMEM_SZ  102400

#define SW128(b) ((b) ^ (((b) >> 3) & 0x70))

__device__ __forceinline__ u32 smem_u32(const void* p) {
    u32 a;
    asm("{ .reg .u64 t; cvta.to.shared.u64 t, %1; cvt.u32.u64 %0, t; }" : "=r"(a) : "l"(p));
    return a;
}
#define LDSM_X4(r, addr) \
    asm volatile("ldmatrix.sync.aligned.m8n8.x4.shared.b16 {%0,%1,%2,%3}, [%4];" \
        : "=r"((r)[0]), "=r"((r)[1]), "=r"((r)[2]), "=r"((r)[3]) : "r"(addr))
#define MMA_BF16(c, a, b0, b1) \
    asm volatile("mma.sync.aligned.m16n8k16.row.col.f32.bf16.bf16.f32 " \
        "{%0,%1,%2,%3}, {%4,%5,%6,%7}, {%8,%9}, {%0,%1,%2,%3};" \
        : "+f"((c)[0]), "+f"((c)[1]), "+f"((c)[2]), "+f"((c)[3]) \
        : "r"((a)[0]), "r"((a)[1]), "r"((a)[2]), "r"((a)[3]), \
          "r"(b0), "r"(b1))

__device__ __forceinline__ void split3(float x, u32& h0, u32& h1, u32& h2) {
    __nv_bfloat16 b0 = __float2bfloat16(x);
    float f0 = __bfloat162float(b0);
    float r = x - f0;
    __nv_bfloat16 b1 = __float2bfloat16(r);
    float f1 = __bfloat162float(b1);
    __nv_bfloat16 b2 = __float2bfloat16(r - f1);
    h0 = (u32)__bfloat16_as_ushort(b0);
    h1 = (u32)__bfloat16_as_ushort(b1);
    h2 = (u32)__bfloat16_as_ushort(b2);
}
__device__ __forceinline__ float bf_lo(u32 w) {
    return __bfloat162float(__ushort_as_bfloat16((unsigned short)(w & 0xffffu)));
}
__device__ __forceinline__ float bf_hi(u32 w) {
    return __bfloat162float(__ushort_as_bfloat16((unsigned short)(w >> 16)));
}
__device__ __forceinline__ u64 pack_key(float v, u32 k) {
    u32 u = __float_as_uint(v);
    u = (u & 0x80000000u) ? ~u : (u | 0x80000000u);
    return ((u64)u << 32) | (u64)k;
}

// ---------------------------------------------------------------------------
// Kernel 0: zero scratch, ||e||^2, split embeddings into 3 bf16 arrays
// ---------------------------------------------------------------------------
__global__ void k_prep(const float* __restrict__ emb) {
    int t = blockIdx.x * blockDim.x + threadIdx.x;   // 16384 threads
    reinterpret_cast<float4*>(g_dw)[t] = make_float4(0.f, 0.f, 0.f, 0.f);
    {
        int code = t >> 4, dq = t & 15;
        float4 v = __ldg(reinterpret_cast<const float4*>(emb) + t);
        u32 h0[4], h1[4], h2[4];
        split3(v.x, h0[0], h1[0], h2[0]);
        split3(v.y, h0[1], h1[1], h2[1]);
        split3(v.z, h0[2], h1[2], h2[2]);
        split3(v.w, h0[3], h1[3], h2[3]);
        u32 base = code * 32 + dq * 2;
        u32* p0 = reinterpret_cast<u32*>(g_esplit[0]);
        u32* p1 = reinterpret_cast<u32*>(g_esplit[1]);
        u32* p2 = reinterpret_cast<u32*>(g_esplit[2]);
        p0[base] = h0[0] | (h0[1] << 16);  p0[base + 1] = h0[2] | (h0[3] << 16);
        p1[base] = h1[0] | (h1[1] << 16);  p1[base + 1] = h1[2] | (h1[3] << 16);
        p2[base] = h2[0] | (h2[1] << 16);  p2[base + 1] = h2[2] | (h2[3] << 16);
    }
    if (t < KCODES) {
        g_ni[t] = 0.0f;
        const float4* e4 = reinterpret_cast<const float4*>(emb + (size_t)t * DIM);
        float s = 0.0f;
#pragma unroll
        for (int i = 0; i < 16; i++) {
            float4 v = e4[i];
            s += v.x * v.x + v.y * v.y + v.z * v.z + v.w * v.w;
        }
        g_ee[t] = s;
    }
    if (t == 0) g_loss = 0.0f;
}

// ---------------------------------------------------------------------------
// Kernel 1: HMMA distances (6-term bf16 split) + argmin + fused epilogue
//   n-tile PAIRS with 4 independent accumulator chains; LDSM_X4 double-tile
//   B loads; ee staged in smem.
// ---------------------------------------------------------------------------
__global__ __launch_bounds__(NTHR, 2)
void k_main(const float* __restrict__ z, const float* __restrict__ emb,
            float* __restrict__ out) {
    extern __shared__ __align__(16) unsigned char sm[];
    int*   sidx = reinterpret_cast<int*>(sm + B_OFF);     // alias B (post-loop)
    float* lred = reinterpret_cast<float*>(sm + B_OFF + 2048);
    float* ees  = reinterpret_cast<float*>(sm + EE_OFF);

    const u32 smb = smem_u32(sm);
    const int tid  = threadIdx.x;
    const int lane = tid & 31;
    const int wid  = tid >> 5;
    const int wrow = wid * 16;
    const int row0 = blockIdx.x * BM;

    // ---- stage ||e||^2 into smem
    for (int i = tid; i < KCODES; i += NTHR) ees[i] = __ldg(&g_ee[i]);

    // ---- build 3 bf16 A tiles from z (SW128, [128 rows][64 d])
    for (int i = tid; i < BM * 16; i += NTHR) {
        int m = i >> 4, dq = i & 15;
        float4 v = *reinterpret_cast<const float4*>(z + (size_t)(row0 + m) * DIM + dq * 4);
        u32 h0[4], h1[4], h2[4];
        split3(v.x, h0[0], h1[0], h2[0]);
        split3(v.y, h0[1], h1[1], h2[1]);
        split3(v.z, h0[2], h1[2], h2[2]);
        split3(v.w, h0[3], h1[3], h2[3]);
        u32 sw = SW128((u32)(m * 128 + dq * 8));
#pragma unroll
        for (int t = 0; t < 3; t++) {
            u32* hh = (t == 0) ? h0 : (t == 1) ? h1 : h2;
            u32* dst = reinterpret_cast<u32*>(sm + A_OFF + t * 16384 + sw);
            dst[0] = hh[0] | (hh[1] << 16);
            dst[1] = hh[2] | (hh[3] << 16);
        }
    }
    __syncthreads();

    // ---- load A fragments into registers (persist for whole kernel)
    u32 afr[3][4][4];
    {
        int g = lane >> 3;
        int arow = wrow + (g & 1) * 8 + (lane & 7);
        int acol = (g >> 1) * 16;
#pragma unroll
        for (int t = 0; t < 3; t++)
#pragma unroll
            for (int kt = 0; kt < 4; kt++) {
                u32 addr = smb + A_OFF + t * 16384 +
                           SW128((u32)(arow * 128 + kt * 32 + acol));
                LDSM_X4(afr[t][kt], addr);
            }
    }

    float best0 = 3.4e38f, best1 = 3.4e38f;
    u32   idx0 = 0, idx1 = 0;

    // B x4 addressing: lanes 0-15 -> tile A (rows p*16..+7), 16-31 -> tile B (+8)
    const int brow    = lane & 7;
    const int bcolsel = ((lane >> 3) & 1) * 16;
    const int btile   = (lane >> 4) * 8;
    const int term_order[6] = {0, 3, 1, 4, 2, 5};   // interleave acc0/acc1 groups
    const int TA[6] = {2, 0, 1, 1, 0, 0};           // small terms in acc0 group head
    const int TB[6] = {0, 2, 1, 0, 1, 0};

    for (int c = 0; c < NCHUNK; c++) {
        __syncthreads();   // previous chunk's ldmatrix reads done
        // ---- stage B chunk (3 terms x 128 codes x 128B) swizzled
        for (int u = tid; u < 3072; u += NTHR) {
            int term = u >> 10;
            int rem  = u & 1023;
            int krow = rem >> 3;
            int seg  = rem & 7;
            uint4 v = __ldg(&g_esplit[term][(c * NCK + krow) * 8 + seg]);
            u32 sw = SW128((u32)(krow * 128 + seg * 16));
            *reinterpret_cast<uint4*>(sm + B_OFF + term * 16384 + sw) = v;
        }
        __syncthreads();

        for (int p = 0; p < 8; p++) {        // n-tile pairs: tiles 2p, 2p+1
            float ccA0[4] = {0, 0, 0, 0}, ccA1[4] = {0, 0, 0, 0};
            float ccB0[4] = {0, 0, 0, 0}, ccB1[4] = {0, 0, 0, 0};
            int rbase = (p * 16 + btile + brow) * 128 + bcolsel;

#pragma unroll
            for (int h = 0; h < 2; h++) {    // k-halves: kt {2h, 2h+1}
                // 6 LDSM_X4: [term][kt-in-half]; regs 0,1 = tileA, 2,3 = tileB
                u32 bb[3][2][4];
#pragma unroll
                for (int t = 0; t < 3; t++)
#pragma unroll
                    for (int q = 0; q < 2; q++) {
                        int kt = h * 2 + q;
                        u32 addr = smb + B_OFF + t * 16384 +
                                   SW128((u32)(rbase + kt * 32));
                        LDSM_X4(bb[t][q], addr);
                    }
#pragma unroll
                for (int q = 0; q < 2; q++) {
                    int kt = h * 2 + q;
#pragma unroll
                    for (int o = 0; o < 6; o++) {
                        int t = term_order[o];
                        const u32* a = afr[TA[t]][kt];
                        const u32* b = bb[TB[t]][q];
                        if (t < 3) {
                            MMA_BF16(ccA0, a, b[0], b[1]);
                            MMA_BF16(ccB0, a, b[2], b[3]);
                        } else {
                            MMA_BF16(ccA1, a, b[0], b[1]);
                            MMA_BF16(ccB1, a, b[2], b[3]);
                        }
                    }
                }
            }

            // dist = ||e||^2 - 2*dot; rows lane>>2 (+8), cols 2*(lane&3)+{0,1}
            u32 kcA = (u32)(c * NCK + p * 16 + 2 * (lane & 3));
            u32 kcB = kcA + 8;
            float eA0 = ees[kcA], eA1 = ees[kcA + 1];
            float eB0 = ees[kcB], eB1 = ees[kcB + 1];
#pragma unroll
            for (int half = 0; half < 2; half++) {
                float c0 = (half ? ccA0[2] + ccA1[2] : ccA0[0] + ccA1[0]);
                float c1 = (half ? ccA0[3] + ccA1[3] : ccA0[1] + ccA1[1]);
                float d0 = fmaf(-2.0f, c0, eA0);
                float d1 = fmaf(-2.0f, c1, eA1);
                float cv = (d1 < d0) ? d1 : d0;
                u32   ck = (d1 < d0) ? kcA + 1 : kcA;
                if (half == 0) { if (cv < best0) { best0 = cv; idx0 = ck; } }
                else           { if (cv < best1) { best1 = cv; idx1 = ck; } }
            }
#pragma unroll
            for (int half = 0; half < 2; half++) {
                float c0 = (half ? ccB0[2] + ccB1[2] : ccB0[0] + ccB1[0]);
                float c1 = (half ? ccB0[3] + ccB1[3] : ccB0[1] + ccB1[1]);
                float d0 = fmaf(-2.0f, c0, eB0);
                float d1 = fmaf(-2.0f, c1, eB1);
                float cv = (d1 < d0) ? d1 : d0;
                u32   ck = (d1 < d0) ? kcB + 1 : kcB;
                if (half == 0) { if (cv < best0) { best0 = cv; idx0 = ck; } }
                else           { if (cv < best1) { best1 = cv; idx1 = ck; } }
            }
        }
    }

    // ---- reduce argmin across the 4 lanes sharing each row
    u64 key0 = pack_key(best0, idx0);
    u64 key1 = pack_key(best1, idx1);
#pragma unroll
    for (int o = 1; o <= 2; o <<= 1) {
        u64 t0 = __shfl_xor_sync(0xFFFFFFFFu, key0, o);
        u64 t1 = __shfl_xor_sync(0xFFFFFFFFu, key1, o);
        if (t0 < key0) key0 = t0;
        if (t1 < key1) key1 = t1;
    }
    __syncthreads();   // all mainloop B reads complete -> safe to alias
    if ((lane & 3) == 0) {
        int r0 = wrow + (lane >> 2);
        int i0 = (int)(key0 & 0xFFFFFFFFull);
        int i1 = (int)(key1 & 0xFFFFFFFFull);
        sidx[r0]     = i0;
        sidx[r0 + 8] = i1;
        out[O_IDX + row0 + r0]     = (float)i0;
        out[O_IDX + row0 + r0 + 8] = (float)i1;
        atomicAdd(&g_ni[i0], 1.0f);
        atomicAdd(&g_ni[i1], 1.0f);
    }
    __syncthreads();

    // ---- fused epilogue: reconstruct z from A tiles (z = b0+b1+b2, ~1e-8 err)
    float lacc = 0.0f;
    for (int i = tid; i < BM * 32; i += NTHR) {   // (d-pair, m): m fast
        int d2 = i >> 7;          // 0..31 -> d = 2*d2
        int m  = i & 127;
        u32 sw = SW128((u32)(m * 128 + d2 * 4));
        u32 w0 = *reinterpret_cast<u32*>(sm + A_OFF + sw);
        u32 w1 = *reinterpret_cast<u32*>(sm + A_OFF + 16384 + sw);
        u32 w2 = *reinterpret_cast<u32*>(sm + A_OFF + 32768 + sw);
        float zlo = bf_lo(w0) + bf_lo(w1) + bf_lo(w2);
        float zhi = bf_hi(w0) + bf_hi(w1) + bf_hi(w2);
        int idx = sidx[m];
        int d = d2 * 2;
        float2 q = __ldg(reinterpret_cast<const float2*>(emb + (size_t)idx * DIM + d));
        float dlo = q.x - zlo, dhi = q.y - zhi;
        lacc += dlo * dlo + dhi * dhi;
        int row = row0 + m;
        int b = row >> 10, hw = row & 1023;
        size_t obase = ((size_t)(b * DIM + d) << 10) + hw;
        out[O_QV + obase]        = zlo + dlo;
        out[O_QV + obase + 1024] = zhi + dhi;
        atomicAdd(&g_dw[idx * DIM + d],     zlo);
        atomicAdd(&g_dw[idx * DIM + d + 1], zhi);
    }
#pragma unroll
    for (int o = 16; o > 0; o >>= 1) lacc += __shfl_xor_sync(0xFFFFFFFFu, lacc, o);
    if (lane == 0) lred[wid] = lacc;
    __syncthreads();
    if (tid == 0) {
        float s = 0.0f;
#pragma unroll
        for (int w = 0; w < NTHR / 32; w++) s += lred[w];
        atomicAdd(&g_loss, s);
    }
}

// ---------------------------------------------------------------------------
// Kernel 2: smoothing + EMA + new embeddings
// ---------------------------------------------------------------------------
__global__ __launch_bounds__(256)
void k_final(const float* __restrict__ cs, const float* __restrict__ ema,
             float* __restrict__ out) {
    __shared__ float red[8];
    const int tid = threadIdx.x;

    float part = 0.0f;
#pragma unroll
    for (int k = tid; k < KCODES; k += 256)
        part += cs[k] * 0.99f + g_ni[k] * 0.01f;
#pragma unroll
    for (int o = 16; o > 0; o >>= 1) part += __shfl_xor_sync(0xFFFFFFFFu, part, o);
    if ((tid & 31) == 0) red[tid >> 5] = part;
    __syncthreads();
    float n = 0.0f;
#pragma unroll
    for (int w = 0; w < 8; w++) n += red[w];

    if (blockIdx.x == 0 && tid == 0)
        out[O_LOSS] = 0.25f * g_loss / 2097152.0f;

    const int i0 = (blockIdx.x * 256 + tid) * 4;
    const int k  = i0 >> 6;
    float raw = cs[k] * 0.99f + g_ni[k] * 0.01f;
    float smooth = (raw + 1e-5f) / (n + 1024.0f * 1e-5f) * n;
    if ((i0 & 63) == 0) out[O_CL + k] = smooth;

    float4 ev = *reinterpret_cast<const float4*>(ema + i0);
    float4 dv = *reinterpret_cast<const float4*>(g_dw + i0);
    float inv = 1.0f / smooth;
    float ne0 = ev.x * 0.99f + dv.x * 0.01f;
    float ne1 = ev.y * 0.99f + dv.y * 0.01f;
    float ne2 = ev.z * 0.99f + dv.z * 0.01f;
    float ne3 = ev.w * 0.99f + dv.w * 0.01f;
    out[O_EMA + i0 + 0] = ne0;  out[O_EMB + i0 + 0] = ne0 * inv;
    out[O_EMA + i0 + 1] = ne1;  out[O_EMB + i0 + 1] = ne1 * inv;
    out[O_EMA + i0 + 2] = ne2;  out[O_EMB + i0 + 2] = ne2 * inv;
    out[O_EMA + i0 + 3] = ne3;  out[O_EMB + i0 + 3] = ne3 * inv;
}

// ---------------------------------------------------------------------------
extern "C" void kernel_launch(void* const* d_in, const int* in_sizes, int n_in,
                              void* d_out, int out_size) {
    const float* z   = (const float*)d_in[0];
    const float* emb = (const float*)d_in[1];
    const float* cs  = (const float*)d_in[2];
    const float* ema = (const float*)d_in[3];
    float* out = (float*)d_out;

    static bool attr_set = false;
    if (!attr_set) {
        cudaFuncSetAttribute(k_main, cudaFuncAttributeMaxDynamicSharedMemorySize, SMEM_SZ);
        attr_set = true;
    }

    k_prep<<<64, 256>>>(emb);
    k_main<<<N_TOT / BM, NTHR, SMEM_SZ>>>(z, emb, out);
    k_final<<<64, 256>>>(cs, ema, out);
}